// round 17
// baseline (speedup 1.0000x reference)
#include <cuda_runtime.h>
#include <cstdint>

// Problem constants (established world: int32 inputs, float32 output).
#define BATCH 1024
#define TLEN  4096
#define NNEUR 4096
#define NB    16
#define WPN   2115          // ceil(65536/31)

#define SZ_X    4194304
#define SZ_CONN 65536
#define SZ_MEM  8663040

#define NPB   8             // neurons per block
#define THR   512

// Packed x, COLUMN-major: XC[t*32 + w], bit j = x[w*32 + j][t] & 1.
// One column t = 32 consecutive words = 128B line.
__device__ __align__(16) uint32_t XC[4096 * 32];

__global__ void pack_kernel(const int* __restrict__ x) {
    int idx = blockIdx.x * blockDim.x + threadIdx.x;   // 0 .. 131071
    int w = idx >> 12;           // batch word (0..31)
    int t = idx & 4095;
    const int* xb = x + (size_t)w * 32 * TLEN + t;
    uint32_t v = 0;
#pragma unroll
    for (int j = 0; j < 32; j++)
        v |= ((uint32_t)xb[j * TLEN] & 1u) << j;
    XC[t * 32 + w] = v;
}

// 8x8 bit-matrix transpose (Hacker's Delight).
__device__ __forceinline__ unsigned long long tr8(unsigned long long x) {
    unsigned long long t;
    t = (x ^ (x >> 7))  & 0x00AA00AA00AA00AAull; x = x ^ t ^ (t << 7);
    t = (x ^ (x >> 14)) & 0x0000CCCC0000CCCCull; x = x ^ t ^ (t << 14);
    t = (x ^ (x >> 28)) & 0x00000000F0F0F0F0ull; x = x ^ t ^ (t << 28);
    return x;
}

// smem layout (words): rows [0, 16920), conn [16920, 17048). 68192 B total
// -> 3 blocks/SM (vs 2 with the old xcols staging buffer).
#define SM_ROWS_W   (NPB * WPN)          // 16920
#define SM_CONN_OFF (SM_ROWS_W)
#define SM_TOTAL_B  ((SM_CONN_OFF + 128) * 4)

// ---------------------------------------------------------------------------
// Lookup: block = 8 neurons x ALL 1024 batches; memory rows in SHARED.
// v[j] words are read DIRECTLY from XC in global (L2-hot 128B lines,
// 8 sectors per warp-load), overlapping the bulk row load -> smem drops to
// 68.2 KB -> 3 blocks/SM -> 48 warps/SM and a 1.15-wave grid.
// Compute is per-subgroup (pk[4] + wv[8] live) to stay under the 42-reg cap.
// ---------------------------------------------------------------------------
__global__ void __launch_bounds__(THR, 3)
lookup_kernel(const int* __restrict__ conn,
              const int* __restrict__ mem,
              float*     __restrict__ out) {
    extern __shared__ __align__(16) uint32_t sm[];

    const int tid = threadIdx.x;
    const int n0  = blockIdx.x * NPB;

    // Stage conn (128 ints) and sync on it alone (cheap barrier).
    if (tid < 128)
        sm[SM_CONN_OFF + tid] = (uint32_t)conn[n0 * NB + tid];
    __syncthreads();

    const int ng   = tid & 7;           // neuron within block
    const int w    = (tid >> 3) & 31;   // 32-batch word
    const int half = tid >> 8;          // 0/1 -> subgroup bytes {0,1}/{2,3}

    // v loads from global XC (overlap with the row bulk-load below).
    uint32_t v[NB];
#pragma unroll
    for (int j = 0; j < NB; j++) {
        uint32_t t = sm[SM_CONN_OFF + ng * NB + j];
        v[j] = __ldg(XC + t * 32 + w);
    }

    // Bulk-load 8 memory rows (67680 B) as uint4.
    {
        const uint4* src = reinterpret_cast<const uint4*>(mem + (size_t)n0 * WPN);
        uint4* dst = reinterpret_cast<uint4*>(sm);
#pragma unroll
        for (int r = 0; r < 8; r++)
            dst[tid + r * THR] = src[tid + r * THR];
        if (tid < (SM_ROWS_W / 4) - 8 * THR)            // 134 remainder
            dst[tid + 8 * THR] = src[tid + 8 * THR];
    }
    __syncthreads();

    const uint32_t* srow = sm + ng * WPN;
    const int nn = n0 + ng;

#pragma unroll
    for (int s = 0; s < 2; s++) {
        const uint32_t sb = (uint32_t)(half * 2 + s);   // byte index 0..3
        const uint32_t selb = sb | ((4u + sb) << 4);

        uint32_t a_lo = __byte_perm(__byte_perm(v[7],  v[6],  selb),
                                    __byte_perm(v[5],  v[4],  selb), 0x5410);
        uint32_t a_hi = __byte_perm(__byte_perm(v[3],  v[2],  selb),
                                    __byte_perm(v[1],  v[0],  selb), 0x5410);
        uint32_t c_lo = __byte_perm(__byte_perm(v[15], v[14], selb),
                                    __byte_perm(v[13], v[12], selb), 0x5410);
        uint32_t c_hi = __byte_perm(__byte_perm(v[11], v[10], selb),
                                    __byte_perm(v[9],  v[8],  selb), 0x5410);

        unsigned long long A  = ((unsigned long long)a_hi << 32) | a_lo;
        unsigned long long Bm = ((unsigned long long)c_hi << 32) | c_lo;
        A  = tr8(A);    // byte k = addr bits 15..8 for batch (w*32 + sb*8 + k)
        Bm = tr8(Bm);   // byte k = addr bits  7..0

        const uint32_t Ao0 = (uint32_t)A,  Ao1 = (uint32_t)(A >> 32);
        const uint32_t Bo0 = (uint32_t)Bm, Bo1 = (uint32_t)(Bm >> 32);

        uint32_t pk[4];
        pk[0] = __byte_perm(Bo0, Ao0, 0x5140);
        pk[1] = __byte_perm(Bo0, Ao0, 0x7362);
        pk[2] = __byte_perm(Bo1, Ao1, 0x5140);
        pk[3] = __byte_perm(Bo1, Ao1, 0x7362);

        // 8 predicated smem gathers (int32 world: addr%31 >= 16 -> cell 0).
        uint32_t wv[8];
#pragma unroll
        for (int i = 0; i < 8; i++) {
            unsigned a  = (pk[i >> 1] >> ((i & 1) * 16)) & 0xFFFFu;
            unsigned q  = a / 31u;
            unsigned rr = a - q * 31u;
            wv[i] = 0u;
            if (rr < 16u)
                wv[i] = srow[q];
        }

        // Extract + coalesced stores (warp = 8 ng x 4 w -> 4 sectors/inst).
        const int bbase = w * 32 + (int)sb * 8;
#pragma unroll
        for (int i = 0; i < 8; i++) {
            unsigned a  = (pk[i >> 1] >> ((i & 1) * 16)) & 0xFFFFu;
            unsigned q  = a / 31u;
            unsigned rr = a - q * 31u;
            unsigned cell = (wv[i] >> (2u * rr)) & 3u;
            out[(size_t)(bbase + i) * NNEUR + nn] = (float)cell;
        }
    }
}

// ---------------------------------------------------------------------------
extern "C" void kernel_launch(void* const* d_in, const int* in_sizes, int n_in,
                              void* d_out, int out_size) {
    const void* x    = nullptr;
    const void* conn = nullptr;
    const void* mem  = nullptr;
    for (int i = 0; i < n_in; i++) {
        if      (in_sizes[i] == SZ_X)    x    = d_in[i];
        else if (in_sizes[i] == SZ_CONN) conn = d_in[i];
        else if (in_sizes[i] == SZ_MEM)  mem  = d_in[i];
    }
    if (!x || !conn || !mem) { x = d_in[0]; conn = d_in[1]; mem = d_in[2]; }

    static int smem_set = 0;
    if (!smem_set) {
        cudaFuncSetAttribute(lookup_kernel,
                             cudaFuncAttributeMaxDynamicSharedMemorySize,
                             SM_TOTAL_B);
        smem_set = 1;
    }

    pack_kernel<<<512, 256>>>((const int*)x);
    lookup_kernel<<<NNEUR / NPB, THR, SM_TOTAL_B>>>(
        (const int*)conn, (const int*)mem, (float*)d_out);
}